// round 2
// baseline (speedup 1.0000x reference)
#include <cuda_runtime.h>
#include <cuda_bf16.h>

#define HID    1024
#define INTERD 2816
#define BB     4
#define NTOK   32768   // B * N = 4 * 8192
#define ODIM   1024

// ---------------- scratch (static device globals; no allocs) ----------------
__device__ float g_sc[BB * HID];
__device__ float g_h[BB * HID];
__device__ float g_gy[BB * 2 * INTERD];
__device__ float g_u[BB * INTERD];
__device__ float g_z[BB * HID];
__device__ float g_o[BB * 2 * HID];
__device__ float g_mod[BB * 2 * HID];
__device__ float g_part[1024];
__device__ float g_ws[2];                              // [0]=1/clip(mean|w|), [1]=clip(mean|w|)
__device__ __align__(16) signed char g_wq8[(long)ODIM * HID];   // ternary weights int8
__device__ __align__(16) signed char g_q8[(long)NTOK * HID];    // quantized activations int8
__device__ float g_arecip[NTOK];                       // amax/127 * mean|w|

__device__ __forceinline__ float silu_f(float v) { return v / (1.f + expf(-v)); }

// ---------------- tiny elementwise kernels ----------------
__global__ void silu_c_kernel(const float* __restrict__ c) {
    int i = blockIdx.x * 256 + threadIdx.x;
    if (i < BB * HID) g_sc[i] = silu_f(c[i]);
}

__global__ void gateact_kernel() {
    int i = blockIdx.x * 256 + threadIdx.x;
    if (i < BB * INTERD) {
        int b = i / INTERD, j = i - b * INTERD;
        float g = g_gy[b * 2 * INTERD + j];
        float y = g_gy[b * 2 * INTERD + INTERD + j];
        g_u[i] = silu_f(g) * y;
    }
}

// out[b,d] = sum_k A[b,k] * W[d,k] (+bias[d]); ONE warp per d, all 4 batch rows.
// Weight row is read once (not 4x). A rows are tiny and L1/L2-hot.
__global__ void gemm4b_kernel(const float* __restrict__ A, const float* __restrict__ W,
                              const float* __restrict__ bias, float* __restrict__ out,
                              int K, int D) {
    int warp = threadIdx.x >> 5, lane = threadIdx.x & 31;
    int d = blockIdx.x * 8 + warp;
    if (d >= D) return;
    const float4* w4 = (const float4*)(W + (long)d * K);
    const float4* a4 = (const float4*)A;
    int K4 = K >> 2;
    float acc0 = 0.f, acc1 = 0.f, acc2 = 0.f, acc3 = 0.f;
    for (int k = lane; k < K4; k += 32) {
        float4 wv = w4[k];
        float4 a;
        a = a4[k];            acc0 += wv.x*a.x + wv.y*a.y + wv.z*a.z + wv.w*a.w;
        a = a4[K4 + k];       acc1 += wv.x*a.x + wv.y*a.y + wv.z*a.z + wv.w*a.w;
        a = a4[2*K4 + k];     acc2 += wv.x*a.x + wv.y*a.y + wv.z*a.z + wv.w*a.w;
        a = a4[3*K4 + k];     acc3 += wv.x*a.x + wv.y*a.y + wv.z*a.z + wv.w*a.w;
    }
#pragma unroll
    for (int o = 16; o; o >>= 1) {
        acc0 += __shfl_xor_sync(0xffffffffu, acc0, o);
        acc1 += __shfl_xor_sync(0xffffffffu, acc1, o);
        acc2 += __shfl_xor_sync(0xffffffffu, acc2, o);
        acc3 += __shfl_xor_sync(0xffffffffu, acc3, o);
    }
    if (lane == 0) {
        float bv = bias ? bias[d] : 0.f;
        out[d]         = acc0 + bv;
        out[D + d]     = acc1 + bv;
        out[2 * D + d] = acc2 + bv;
        out[3 * D + d] = acc3 + bv;
    }
}

// in-place rmsnorm of g_o rows (len 2048), eps 1e-6, weight w_norm
__global__ void rms4_kernel(const float* __restrict__ w_norm) {
    __shared__ float sm[256];
    int b = blockIdx.x, tid = threadIdx.x;
    float* o = g_o + b * 2048;
    float s = 0.f;
    for (int i = tid; i < 2048; i += 256) { float v = o[i]; s += v * v; }
    sm[tid] = s; __syncthreads();
    for (int st = 128; st > 0; st >>= 1) { if (tid < st) sm[tid] += sm[tid + st]; __syncthreads(); }
    float rstd = rsqrtf(sm[0] * (1.f / 2048.f) + 1e-6f);
    for (int i = tid; i < 2048; i += 256) o[i] = o[i] * rstd * w_norm[i];
}

// ---------------- weight quant (deterministic reduction) ----------------
__global__ void wabs_partial_kernel(const float* __restrict__ w) {
    __shared__ float sm[256];
    int b = blockIdx.x, tid = threadIdx.x;
    const float* p = w + (long)b * 1024;
    float s = 0.f;
    for (int i = tid; i < 1024; i += 256) s += fabsf(p[i]);
    sm[tid] = s; __syncthreads();
    for (int st = 128; st > 0; st >>= 1) { if (tid < st) sm[tid] += sm[tid + st]; __syncthreads(); }
    if (tid == 0) g_part[b] = sm[0];
}

__global__ void wabs_final_kernel() {
    __shared__ float sm[256];
    int tid = threadIdx.x;
    float s = g_part[tid] + g_part[tid + 256] + g_part[tid + 512] + g_part[tid + 768];
    sm[tid] = s; __syncthreads();
    for (int st = 128; st > 0; st >>= 1) { if (tid < st) sm[tid] += sm[tid + st]; __syncthreads(); }
    if (tid == 0) {
        float mean = sm[0] * (1.f / (1024.f * 1024.f));
        float m = fmaxf(mean, 1e-5f);
        g_ws[0] = 1.f / m;
        g_ws[1] = m;
    }
}

__global__ void wquant_kernel(const float* __restrict__ w) {
    int i = blockIdx.x * 256 + threadIdx.x;           // i indexes groups of 4
    if (i < ODIM * HID / 4) {
        float s = g_ws[0];
        const float4 v = ((const float4*)w)[i];
        char4 q;
        q.x = (signed char)fminf(fmaxf(rintf(v.x * s), -1.f), 1.f);
        q.y = (signed char)fminf(fmaxf(rintf(v.y * s), -1.f), 1.f);
        q.z = (signed char)fminf(fmaxf(rintf(v.z * s), -1.f), 1.f);
        q.w = (signed char)fminf(fmaxf(rintf(v.w * s), -1.f), 1.f);
        ((char4*)g_wq8)[i] = q;
    }
}

// ---------------- activation pipeline: LN -> modulate -> RMSNorm -> quant (int8 out) ----------------
__global__ void aq_kernel(const float* __restrict__ x, const float* __restrict__ wbn) {
    __shared__ float sm[256];
    __shared__ float sm2[256];
    int t = blockIdx.x, tid = threadIdx.x;
    int b = t >> 13;
    const float4* xr = (const float4*)(x + (long)t * HID);
    const float* mod = g_mod + b * 2048;              // [0:1024) shift, [1024:2048) scale
    float4 v = xr[tid];
    float s = v.x + v.y + v.z + v.w;
    float s2 = v.x*v.x + v.y*v.y + v.z*v.z + v.w*v.w;
    sm[tid] = s; sm2[tid] = s2; __syncthreads();
    for (int st = 128; st > 0; st >>= 1) {
        if (tid < st) { sm[tid] += sm[tid + st]; sm2[tid] += sm2[tid + st]; }
        __syncthreads();
    }
    float mean = sm[0] * (1.f / HID);
    float var = sm2[0] * (1.f / HID) - mean * mean;
    float rstd = rsqrtf(var + 1e-6f);
    __syncthreads();

    int h0 = tid * 4;
    float m0 = mod[h0], m1 = mod[h0+1], m2 = mod[h0+2], m3 = mod[h0+3];
    float c0 = 1.f + mod[1024+h0], c1 = 1.f + mod[1024+h0+1],
          c2 = 1.f + mod[1024+h0+2], c3 = 1.f + mod[1024+h0+3];
    v.x = (v.x - mean) * rstd * c0 + m0;
    v.y = (v.y - mean) * rstd * c1 + m1;
    v.z = (v.z - mean) * rstd * c2 + m2;
    v.w = (v.w - mean) * rstd * c3 + m3;
    float ms = v.x*v.x + v.y*v.y + v.z*v.z + v.w*v.w;
    sm[tid] = ms; __syncthreads();
    for (int st = 128; st > 0; st >>= 1) { if (tid < st) sm[tid] += sm[tid + st]; __syncthreads(); }
    float rr = rsqrtf(sm[0] * (1.f / HID) + 1e-8f);
    __syncthreads();

    v.x *= rr * wbn[h0];  v.y *= rr * wbn[h0+1];
    v.z *= rr * wbn[h0+2]; v.w *= rr * wbn[h0+3];
    float amax = fmaxf(fmaxf(fabsf(v.x), fabsf(v.y)), fmaxf(fabsf(v.z), fabsf(v.w)));
    sm[tid] = amax; __syncthreads();
    for (int st = 128; st > 0; st >>= 1) { if (tid < st) sm[tid] = fmaxf(sm[tid], sm[tid + st]); __syncthreads(); }
    float am = fmaxf(sm[0], 1e-5f);
    float sa = 127.f / am;
    char4 q;
    q.x = (signed char)fminf(fmaxf(rintf(v.x * sa), -128.f), 127.f);
    q.y = (signed char)fminf(fmaxf(rintf(v.y * sa), -128.f), 127.f);
    q.z = (signed char)fminf(fmaxf(rintf(v.z * sa), -128.f), 127.f);
    q.w = (signed char)fminf(fmaxf(rintf(v.w * sa), -128.f), 127.f);
    ((char4*)(g_q8 + (long)t * HID))[tid] = q;
    if (tid == 0) g_arecip[t] = am * (1.f / 127.f) * g_ws[1];
}

// ---------------- main GEMM: int8 IMMA, exact integer math ----------------
__device__ __forceinline__ void cp16(void* s, const void* g) {
    unsigned sa = (unsigned)__cvta_generic_to_shared(s);
    asm volatile("cp.async.cg.shared.global [%0], [%1], 16;\n" :: "r"(sa), "l"(g));
}

#define NSTAGE 3
#define BK     64
#define SROW   80                  // 64 data bytes + 16 pad (conflict-free 4B LDS)
#define STAGE_BYTES (128 * SROW)   // 10240 per operand per stage

extern __shared__ __align__(16) signed char smem_dyn[];

__global__ void __launch_bounds__(256, 2) bitgemm_i8_kernel(const float* __restrict__ bias,
                                                            float* __restrict__ out) {
    signed char* As = smem_dyn;                               // [NSTAGE][128][SROW]
    signed char* Bs = smem_dyn + NSTAGE * STAGE_BYTES;
    const int tid = threadIdx.x;
    const int lane = tid & 31, warp = tid >> 5;
    const int wm = warp >> 1, wn = warp & 1;                  // 4x2 warps: 32 rows x 64 cols each
    const long arow0 = (long)blockIdx.y * 128;
    const int  brow0 = blockIdx.x * 128;
    const int gr = lane >> 2, tg = lane & 3;

    int acc[2][8][4];
#pragma unroll
    for (int i = 0; i < 2; i++)
#pragma unroll
        for (int j = 0; j < 8; j++)
#pragma unroll
            for (int r = 0; r < 4; r++) acc[i][j][r] = 0;

    // prologue: load stages 0..NSTAGE-2
#pragma unroll
    for (int s = 0; s < NSTAGE - 1; s++) {
        int k0 = s * BK;
#pragma unroll
        for (int j = 0; j < 2; j++) {
            int cidx = tid + 256 * j;
            int r = cidx >> 2, kc = (cidx & 3) * 16;
            cp16(As + s * STAGE_BYTES + r * SROW + kc, g_q8 + (arow0 + r) * HID + k0 + kc);
            cp16(Bs + s * STAGE_BYTES + r * SROW + kc, g_wq8 + (long)(brow0 + r) * HID + k0 + kc);
        }
        asm volatile("cp.async.commit_group;\n");
    }

#pragma unroll 1
    for (int kt = 0; kt < 16; kt++) {
        if (kt < 15) asm volatile("cp.async.wait_group %0;\n" :: "n"(NSTAGE - 2));
        else         asm volatile("cp.async.wait_group 0;\n");
        __syncthreads();

        // issue loads for stage kt+NSTAGE-1 (overwrites buffer read at kt-1; sync above protects)
        if (kt + NSTAGE - 1 < 16) {
            int s = (kt + NSTAGE - 1) % NSTAGE;
            int k0 = (kt + NSTAGE - 1) * BK;
#pragma unroll
            for (int j = 0; j < 2; j++) {
                int cidx = tid + 256 * j;
                int r = cidx >> 2, kc = (cidx & 3) * 16;
                cp16(As + s * STAGE_BYTES + r * SROW + kc, g_q8 + (arow0 + r) * HID + k0 + kc);
                cp16(Bs + s * STAGE_BYTES + r * SROW + kc, g_wq8 + (long)(brow0 + r) * HID + k0 + kc);
            }
            asm volatile("cp.async.commit_group;\n");
        }

        const signed char* Ab = As + (kt % NSTAGE) * STAGE_BYTES;
        const signed char* Bb = Bs + (kt % NSTAGE) * STAGE_BYTES;
#pragma unroll
        for (int ks = 0; ks < 2; ks++) {
            const int kb = ks * 32;
            unsigned afr[2][4];
#pragma unroll
            for (int i = 0; i < 2; i++) {
                int r = wm * 32 + i * 16;
                afr[i][0] = *(const unsigned*)(Ab + (r + gr) * SROW + kb + tg * 4);
                afr[i][1] = *(const unsigned*)(Ab + (r + gr + 8) * SROW + kb + tg * 4);
                afr[i][2] = *(const unsigned*)(Ab + (r + gr) * SROW + kb + 16 + tg * 4);
                afr[i][3] = *(const unsigned*)(Ab + (r + gr + 8) * SROW + kb + 16 + tg * 4);
            }
#pragma unroll
            for (int j = 0; j < 8; j++) {
                int nrow = wn * 64 + j * 8 + gr;
                unsigned b0 = *(const unsigned*)(Bb + nrow * SROW + kb + tg * 4);
                unsigned b1 = *(const unsigned*)(Bb + nrow * SROW + kb + 16 + tg * 4);
#pragma unroll
                for (int i = 0; i < 2; i++) {
                    asm volatile(
                        "mma.sync.aligned.m16n8k32.row.col.s32.s8.s8.s32 "
                        "{%0,%1,%2,%3}, {%4,%5,%6,%7}, {%8,%9}, {%0,%1,%2,%3};"
                        : "+r"(acc[i][j][0]), "+r"(acc[i][j][1]),
                          "+r"(acc[i][j][2]), "+r"(acc[i][j][3])
                        : "r"(afr[i][0]), "r"(afr[i][1]), "r"(afr[i][2]), "r"(afr[i][3]),
                          "r"(b0), "r"(b1));
                }
            }
        }
    }

    // epilogue: exact int -> fp32 dequant + bias
#pragma unroll
    for (int i = 0; i < 2; i++) {
        long row = arow0 + wm * 32 + i * 16 + gr;
        float r0 = g_arecip[row];
        float r1 = g_arecip[row + 8];
#pragma unroll
        for (int j = 0; j < 8; j++) {
            int col = brow0 + wn * 64 + j * 8 + 2 * tg;
            float b0v = bias[col], b1v = bias[col + 1];
            float2 lo = make_float2((float)acc[i][j][0] * r0 + b0v, (float)acc[i][j][1] * r0 + b1v);
            float2 hi = make_float2((float)acc[i][j][2] * r1 + b0v, (float)acc[i][j][3] * r1 + b1v);
            *(float2*)(out + row * ODIM + col)       = lo;
            *(float2*)(out + (row + 8) * ODIM + col) = hi;
        }
    }
}

// ---------------- launch ----------------
extern "C" void kernel_launch(void* const* d_in, const int* in_sizes, int n_in,
                              void* d_out, int out_size) {
    const float* x        = (const float*)d_in[0];
    const float* c        = (const float*)d_in[1];
    const float* w_input  = (const float*)d_in[2];
    const float* w_gate   = (const float*)d_in[3];
    const float* w_down   = (const float*)d_in[4];
    const float* w_output = (const float*)d_in[5];
    const float* b_output = (const float*)d_in[6];
    const float* w_norm   = (const float*)d_in[7];
    const float* w_outp   = (const float*)d_in[8];
    const float* b_outp   = (const float*)d_in[9];
    const float* w_bit    = (const float*)d_in[10];
    const float* b_bit    = (const float*)d_in[11];
    const float* w_bn     = (const float*)d_in[12];
    float* out = (float*)d_out;

    float *p_sc, *p_h, *p_gy, *p_u, *p_z, *p_o, *p_mod;
    cudaGetSymbolAddress((void**)&p_sc,  g_sc);
    cudaGetSymbolAddress((void**)&p_h,   g_h);
    cudaGetSymbolAddress((void**)&p_gy,  g_gy);
    cudaGetSymbolAddress((void**)&p_u,   g_u);
    cudaGetSymbolAddress((void**)&p_z,   g_z);
    cudaGetSymbolAddress((void**)&p_o,   g_o);
    cudaGetSymbolAddress((void**)&p_mod, g_mod);

    // weight quant path
    wabs_partial_kernel<<<1024, 256>>>(w_bit);
    wabs_final_kernel<<<1, 256>>>();
    wquant_kernel<<<(ODIM * HID / 4) / 256, 256>>>(w_bit);

    // modulation chain (B=4); each weight matrix read exactly once
    silu_c_kernel<<<16, 256>>>(c);
    gemm4b_kernel<<<128, 256>>>(p_sc, w_input, nullptr, p_h, HID, HID);
    gemm4b_kernel<<<704, 256>>>(p_h, w_gate, nullptr, p_gy, HID, 2 * INTERD);
    gateact_kernel<<<44, 256>>>();
    gemm4b_kernel<<<128, 256>>>(p_u, w_down, nullptr, p_z, INTERD, HID);
    gemm4b_kernel<<<256, 256>>>(p_z, w_output, b_output, p_o, HID, 2 * HID);
    rms4_kernel<<<4, 256>>>(w_norm);
    gemm4b_kernel<<<256, 256>>>(p_o, w_outp, b_outp, p_mod, 2 * HID, 2 * HID);

    // per-token normalize + int8 quantize
    aq_kernel<<<NTOK, 256>>>(x, w_bn);

    // main GEMM
    static const int smem_bytes = 2 * NSTAGE * STAGE_BYTES;   // 61440
    cudaFuncSetAttribute(bitgemm_i8_kernel, cudaFuncAttributeMaxDynamicSharedMemorySize, smem_bytes);
    dim3 ggrid(8, 256);    // n-tiles fastest: 8 column tiles share the A m-tile via L2
    bitgemm_i8_kernel<<<ggrid, 256, smem_bytes>>>(b_bit, out);
}

// round 8
// speedup vs baseline: 1.4336x; 1.4336x over previous
#include <cuda_runtime.h>
#include <cuda_bf16.h>
#include <cstdint>

#define HID    1024
#define INTERD 2816
#define BB     4
#define NTOK   32768   // B * N = 4 * 8192
#define ODIM   1024

// ---------------- scratch (static device globals; no allocs) ----------------
__device__ float g_sc[BB * HID];
__device__ float g_h[BB * HID];
__device__ float g_gy[BB * 2 * INTERD];
__device__ float g_u[BB * INTERD];
__device__ float g_z[BB * HID];
__device__ float g_o[BB * 2 * HID];
__device__ float g_mod[BB * 2 * HID];
__device__ float g_part[1024];
__device__ float g_ws[2];                              // [0]=1/clip(mean|w|), [1]=clip(mean|w|)
__device__ __align__(16) __nv_bfloat16 g_wq[(long)ODIM * HID];   // ternary weights bf16
__device__ __align__(16) __nv_bfloat16 g_q[(long)NTOK * HID];    // quantized activations bf16 (ints)
__device__ float g_arecip[NTOK];                       // amax/127 * mean|w|

__device__ __forceinline__ float silu_f(float v) { return v / (1.f + expf(-v)); }

// ---------------- tiny elementwise kernels ----------------
__global__ void silu_c_kernel(const float* __restrict__ c) {
    int i = blockIdx.x * 256 + threadIdx.x;
    if (i < BB * HID) g_sc[i] = silu_f(c[i]);
}

__global__ void gateact_kernel() {
    int i = blockIdx.x * 256 + threadIdx.x;
    if (i < BB * INTERD) {
        int b = i / INTERD, j = i - b * INTERD;
        float g = g_gy[b * 2 * INTERD + j];
        float y = g_gy[b * 2 * INTERD + INTERD + j];
        g_u[i] = silu_f(g) * y;
    }
}

// out[b,d] = sum_k A[b,k]*W[d,k] (+bias[d]); one warp per d, all 4 batch rows.
// Weight row read once (not 4x); A rows tiny and cache-hot. (Runtime-verified in R2.)
__global__ void gemm4b_kernel(const float* __restrict__ A, const float* __restrict__ W,
                              const float* __restrict__ bias, float* __restrict__ out,
                              int K, int D) {
    int warp = threadIdx.x >> 5, lane = threadIdx.x & 31;
    int d = blockIdx.x * 8 + warp;
    if (d >= D) return;
    const float4* w4 = (const float4*)(W + (long)d * K);
    const float4* a4 = (const float4*)A;
    int K4 = K >> 2;
    float acc0 = 0.f, acc1 = 0.f, acc2 = 0.f, acc3 = 0.f;
    for (int k = lane; k < K4; k += 32) {
        float4 wv = w4[k];
        float4 a;
        a = a4[k];          acc0 += wv.x*a.x + wv.y*a.y + wv.z*a.z + wv.w*a.w;
        a = a4[K4 + k];     acc1 += wv.x*a.x + wv.y*a.y + wv.z*a.z + wv.w*a.w;
        a = a4[2*K4 + k];   acc2 += wv.x*a.x + wv.y*a.y + wv.z*a.z + wv.w*a.w;
        a = a4[3*K4 + k];   acc3 += wv.x*a.x + wv.y*a.y + wv.z*a.z + wv.w*a.w;
    }
#pragma unroll
    for (int o = 16; o; o >>= 1) {
        acc0 += __shfl_xor_sync(0xffffffffu, acc0, o);
        acc1 += __shfl_xor_sync(0xffffffffu, acc1, o);
        acc2 += __shfl_xor_sync(0xffffffffu, acc2, o);
        acc3 += __shfl_xor_sync(0xffffffffu, acc3, o);
    }
    if (lane == 0) {
        float bv = bias ? bias[d] : 0.f;
        out[d] = acc0 + bv; out[D + d] = acc1 + bv;
        out[2 * D + d] = acc2 + bv; out[3 * D + d] = acc3 + bv;
    }
}

__global__ void rms4_kernel(const float* __restrict__ w_norm) {
    __shared__ float sm[256];
    int b = blockIdx.x, tid = threadIdx.x;
    float* o = g_o + b * 2048;
    float s = 0.f;
    for (int i = tid; i < 2048; i += 256) { float v = o[i]; s += v * v; }
    sm[tid] = s; __syncthreads();
    for (int st = 128; st > 0; st >>= 1) { if (tid < st) sm[tid] += sm[tid + st]; __syncthreads(); }
    float rstd = rsqrtf(sm[0] * (1.f / 2048.f) + 1e-6f);
    for (int i = tid; i < 2048; i += 256) o[i] = o[i] * rstd * w_norm[i];
}

// ---------------- weight quant (deterministic reduction) ----------------
__global__ void wabs_partial_kernel(const float* __restrict__ w) {
    __shared__ float sm[256];
    int b = blockIdx.x, tid = threadIdx.x;
    const float* p = w + (long)b * 1024;
    float s = 0.f;
    for (int i = tid; i < 1024; i += 256) s += fabsf(p[i]);
    sm[tid] = s; __syncthreads();
    for (int st = 128; st > 0; st >>= 1) { if (tid < st) sm[tid] += sm[tid + st]; __syncthreads(); }
    if (tid == 0) g_part[b] = sm[0];
}

__global__ void wabs_final_kernel() {
    __shared__ float sm[256];
    int tid = threadIdx.x;
    float s = g_part[tid] + g_part[tid + 256] + g_part[tid + 512] + g_part[tid + 768];
    sm[tid] = s; __syncthreads();
    for (int st = 128; st > 0; st >>= 1) { if (tid < st) sm[tid] += sm[tid + st]; __syncthreads(); }
    if (tid == 0) {
        float mean = sm[0] * (1.f / (1024.f * 1024.f));
        float m = fmaxf(mean, 1e-5f);
        g_ws[0] = 1.f / m;
        g_ws[1] = m;
    }
}

__global__ void wquant_kernel(const float* __restrict__ w) {
    int i = blockIdx.x * 256 + threadIdx.x;           // groups of 4
    if (i < ODIM * HID / 4) {
        float s = g_ws[0];
        const float4 v = ((const float4*)w)[i];
        __nv_bfloat162 lo, hi;
        lo.x = __float2bfloat16(fminf(fmaxf(rintf(v.x * s), -1.f), 1.f));
        lo.y = __float2bfloat16(fminf(fmaxf(rintf(v.y * s), -1.f), 1.f));
        hi.x = __float2bfloat16(fminf(fmaxf(rintf(v.z * s), -1.f), 1.f));
        hi.y = __float2bfloat16(fminf(fmaxf(rintf(v.w * s), -1.f), 1.f));
        ((__nv_bfloat162*)g_wq)[i * 2]     = lo;
        ((__nv_bfloat162*)g_wq)[i * 2 + 1] = hi;
    }
}

// ---------------- activation pipeline: LN -> modulate -> RMSNorm -> quant ----------------
__global__ void aq_kernel(const float* __restrict__ x, const float* __restrict__ wbn) {
    __shared__ float sm[256];
    __shared__ float sm2[256];
    int t = blockIdx.x, tid = threadIdx.x;
    int b = t >> 13;
    const float4* xr = (const float4*)(x + (long)t * HID);
    const float* mod = g_mod + b * 2048;              // [0:1024) shift, [1024:2048) scale
    float4 v = xr[tid];
    float s = v.x + v.y + v.z + v.w;
    float s2 = v.x*v.x + v.y*v.y + v.z*v.z + v.w*v.w;
    sm[tid] = s; sm2[tid] = s2; __syncthreads();
    for (int st = 128; st > 0; st >>= 1) {
        if (tid < st) { sm[tid] += sm[tid + st]; sm2[tid] += sm2[tid + st]; }
        __syncthreads();
    }
    float mean = sm[0] * (1.f / HID);
    float var = sm2[0] * (1.f / HID) - mean * mean;
    float rstd = rsqrtf(var + 1e-6f);
    __syncthreads();

    int h0 = tid * 4;
    v.x = (v.x - mean) * rstd * (1.f + mod[1024+h0])   + mod[h0];
    v.y = (v.y - mean) * rstd * (1.f + mod[1024+h0+1]) + mod[h0+1];
    v.z = (v.z - mean) * rstd * (1.f + mod[1024+h0+2]) + mod[h0+2];
    v.w = (v.w - mean) * rstd * (1.f + mod[1024+h0+3]) + mod[h0+3];
    float ms = v.x*v.x + v.y*v.y + v.z*v.z + v.w*v.w;
    sm[tid] = ms; __syncthreads();
    for (int st = 128; st > 0; st >>= 1) { if (tid < st) sm[tid] += sm[tid + st]; __syncthreads(); }
    float rr = rsqrtf(sm[0] * (1.f / HID) + 1e-8f);
    __syncthreads();

    v.x *= rr * wbn[h0];   v.y *= rr * wbn[h0+1];
    v.z *= rr * wbn[h0+2]; v.w *= rr * wbn[h0+3];
    float amax = fmaxf(fmaxf(fabsf(v.x), fabsf(v.y)), fmaxf(fabsf(v.z), fabsf(v.w)));
    sm[tid] = amax; __syncthreads();
    for (int st = 128; st > 0; st >>= 1) { if (tid < st) sm[tid] = fmaxf(sm[tid], sm[tid + st]); __syncthreads(); }
    float am = fmaxf(sm[0], 1e-5f);
    float sa = 127.f / am;
    __nv_bfloat162 q0, q1;
    q0.x = __float2bfloat16(fminf(fmaxf(rintf(v.x * sa), -128.f), 127.f));
    q0.y = __float2bfloat16(fminf(fmaxf(rintf(v.y * sa), -128.f), 127.f));
    q1.x = __float2bfloat16(fminf(fmaxf(rintf(v.z * sa), -128.f), 127.f));
    q1.y = __float2bfloat16(fminf(fmaxf(rintf(v.w * sa), -128.f), 127.f));
    __nv_bfloat162* qp = (__nv_bfloat162*)(g_q + (long)t * HID);
    qp[tid * 2]     = q0;
    qp[tid * 2 + 1] = q1;
    if (tid == 0) g_arecip[t] = am * (1.f / 127.f) * g_ws[1];
}

// ---------------- main GEMM: bf16 mma.sync (R1, runtime-verified @460us) ----------------
__device__ __forceinline__ void cp16(void* s, const void* g) {
    unsigned sa = (unsigned)__cvta_generic_to_shared(s);
    asm volatile("cp.async.cg.shared.global [%0], [%1], 16;\n" :: "r"(sa), "l"(g));
}

#define GLDS 40   // padded row stride in bf16 (conflict-free fragment loads)

__global__ void __launch_bounds__(256, 2) bitgemm_kernel(const float* __restrict__ bias,
                                                         float* __restrict__ out) {
    __shared__ __align__(16) __nv_bfloat16 As[2][128 * GLDS];
    __shared__ __align__(16) __nv_bfloat16 Bs[2][128 * GLDS];
    const int tid = threadIdx.x;
    const int lane = tid & 31, warp = tid >> 5;
    const int wm = warp >> 1, wn = warp & 1;      // 4x2 warp grid: 32 rows x 64 cols per warp
    const long arow0 = (long)blockIdx.y * 128;
    const int brow0 = blockIdx.x * 128;
    const int g = lane >> 2, tg = lane & 3;

    float acc[2][8][4];
#pragma unroll
    for (int i = 0; i < 2; i++)
#pragma unroll
        for (int j = 0; j < 8; j++)
#pragma unroll
            for (int r = 0; r < 4; r++) acc[i][j][r] = 0.f;

    {
#pragma unroll
        for (int j = 0; j < 2; j++) {
            int cidx = tid + 256 * j;
            int r = cidx >> 2; int kc = (cidx & 3) * 8;
            cp16(&As[0][r * GLDS + kc], g_q + (arow0 + r) * HID + kc);
            cp16(&Bs[0][r * GLDS + kc], g_wq + (long)(brow0 + r) * HID + kc);
        }
        asm volatile("cp.async.commit_group;\n");
    }

#pragma unroll 1
    for (int kt = 0; kt < 32; kt++) {
        if (kt < 31) {
            int k0 = (kt + 1) * 32;
            int stage = (kt + 1) & 1;
#pragma unroll
            for (int j = 0; j < 2; j++) {
                int cidx = tid + 256 * j;
                int r = cidx >> 2; int kc = (cidx & 3) * 8;
                cp16(&As[stage][r * GLDS + kc], g_q + (arow0 + r) * HID + k0 + kc);
                cp16(&Bs[stage][r * GLDS + kc], g_wq + (long)(brow0 + r) * HID + k0 + kc);
            }
            asm volatile("cp.async.commit_group;\n");
            asm volatile("cp.async.wait_group 1;\n");
        } else {
            asm volatile("cp.async.wait_group 0;\n");
        }
        __syncthreads();

        const __nv_bfloat16* Ab = As[kt & 1];
        const __nv_bfloat16* Bb = Bs[kt & 1];
#pragma unroll
        for (int ks = 0; ks < 2; ks++) {
            const int kb = ks * 16;
            unsigned afr[2][4];
#pragma unroll
            for (int i = 0; i < 2; i++) {
                int r = wm * 32 + i * 16;
                afr[i][0] = *(const unsigned*)(Ab + (r + g) * GLDS + kb + 2 * tg);
                afr[i][1] = *(const unsigned*)(Ab + (r + g + 8) * GLDS + kb + 2 * tg);
                afr[i][2] = *(const unsigned*)(Ab + (r + g) * GLDS + kb + 2 * tg + 8);
                afr[i][3] = *(const unsigned*)(Ab + (r + g + 8) * GLDS + kb + 2 * tg + 8);
            }
#pragma unroll
            for (int j = 0; j < 8; j++) {
                int nrow = wn * 64 + j * 8 + g;
                unsigned b0 = *(const unsigned*)(Bb + nrow * GLDS + kb + 2 * tg);
                unsigned b1 = *(const unsigned*)(Bb + nrow * GLDS + kb + 2 * tg + 8);
#pragma unroll
                for (int i = 0; i < 2; i++) {
                    asm volatile(
                        "mma.sync.aligned.m16n8k16.row.col.f32.bf16.bf16.f32 "
                        "{%0,%1,%2,%3}, {%4,%5,%6,%7}, {%8,%9}, {%0,%1,%2,%3};"
                        : "+f"(acc[i][j][0]), "+f"(acc[i][j][1]),
                          "+f"(acc[i][j][2]), "+f"(acc[i][j][3])
                        : "r"(afr[i][0]), "r"(afr[i][1]), "r"(afr[i][2]), "r"(afr[i][3]),
                          "r"(b0), "r"(b1));
                }
            }
        }
        __syncthreads();
    }

    // epilogue: exact int accum -> fp32 dequant per token + bias
#pragma unroll
    for (int i = 0; i < 2; i++) {
        long row = arow0 + wm * 32 + i * 16 + g;
        float r0 = g_arecip[row];
        float r1 = g_arecip[row + 8];
#pragma unroll
        for (int j = 0; j < 8; j++) {
            int col = brow0 + wn * 64 + j * 8 + 2 * tg;
            float b0v = bias[col], b1v = bias[col + 1];
            out[row * ODIM + col]           = acc[i][j][0] * r0 + b0v;
            out[row * ODIM + col + 1]       = acc[i][j][1] * r0 + b1v;
            out[(row + 8) * ODIM + col]     = acc[i][j][2] * r1 + b0v;
            out[(row + 8) * ODIM + col + 1] = acc[i][j][3] * r1 + b1v;
        }
    }
}

// ---------------- launch ----------------
extern "C" void kernel_launch(void* const* d_in, const int* in_sizes, int n_in,
                              void* d_out, int out_size) {
    const float* x        = (const float*)d_in[0];
    const float* c        = (const float*)d_in[1];
    const float* w_input  = (const float*)d_in[2];
    const float* w_gate   = (const float*)d_in[3];
    const float* w_down   = (const float*)d_in[4];
    const float* w_output = (const float*)d_in[5];
    const float* b_output = (const float*)d_in[6];
    const float* w_norm   = (const float*)d_in[7];
    const float* w_outp   = (const float*)d_in[8];
    const float* b_outp   = (const float*)d_in[9];
    const float* w_bit    = (const float*)d_in[10];
    const float* b_bit    = (const float*)d_in[11];
    const float* w_bn     = (const float*)d_in[12];
    float* out = (float*)d_out;

    float *p_sc, *p_h, *p_gy, *p_u, *p_z, *p_o, *p_mod;
    cudaGetSymbolAddress((void**)&p_sc,  g_sc);
    cudaGetSymbolAddress((void**)&p_h,   g_h);
    cudaGetSymbolAddress((void**)&p_gy,  g_gy);
    cudaGetSymbolAddress((void**)&p_u,   g_u);
    cudaGetSymbolAddress((void**)&p_z,   g_z);
    cudaGetSymbolAddress((void**)&p_o,   g_o);
    cudaGetSymbolAddress((void**)&p_mod, g_mod);

    // weight quant path (independent)
    wabs_partial_kernel<<<1024, 256>>>(w_bit);
    wabs_final_kernel<<<1, 256>>>();
    wquant_kernel<<<(ODIM * HID / 4) / 256, 256>>>(w_bit);

    // modulation chain (B=4); each weight matrix read exactly once
    silu_c_kernel<<<16, 256>>>(c);
    gemm4b_kernel<<<128, 256>>>(p_sc, w_input, nullptr, p_h, HID, HID);
    gemm4b_kernel<<<704, 256>>>(p_h, w_gate, nullptr, p_gy, HID, 2 * INTERD);
    gateact_kernel<<<44, 256>>>();
    gemm4b_kernel<<<128, 256>>>(p_u, w_down, nullptr, p_z, INTERD, HID);
    gemm4b_kernel<<<256, 256>>>(p_z, w_output, b_output, p_o, HID, 2 * HID);
    rms4_kernel<<<4, 256>>>(w_norm);
    gemm4b_kernel<<<256, 256>>>(p_o, w_outp, b_outp, p_mod, 2 * HID, 2 * HID);

    // per-token normalize + bf16-int quantize
    aq_kernel<<<NTOK, 256>>>(x, w_bn);

    // main GEMM + dequant epilogue (proven R1 kernel)
    dim3 ggrid(8, 256);   // n-tiles fastest: 8 column tiles share the A m-tile via L2
    bitgemm_kernel<<<ggrid, 256>>>(b_bit, out);
}

// round 9
// speedup vs baseline: 1.8140x; 1.2653x over previous
#include <cuda_runtime.h>
#include <cuda_bf16.h>
#include <cstdint>

#define HID    1024
#define INTERD 2816
#define BB     4
#define NTOK   32768   // B * N = 4 * 8192
#define ODIM   1024

// ---------------- scratch (static device globals; no allocs) ----------------
__device__ float g_sc[BB * HID];
__device__ float g_h[BB * HID];
__device__ float g_gy[BB * 2 * INTERD];
__device__ float g_u[BB * INTERD];
__device__ float g_z[BB * HID];
__device__ float g_o[BB * 2 * HID];
__device__ float g_mod[BB * 2 * HID];
__device__ float g_part[1024];
__device__ float g_ws[2];                              // [0]=1/clip(mean|w|), [1]=clip(mean|w|)
__device__ __align__(16) __nv_bfloat16 g_wq[(long)ODIM * HID];   // ternary weights bf16
__device__ __align__(16) __nv_bfloat16 g_q[(long)NTOK * HID];    // quantized activations bf16 (ints)
__device__ float g_arecip[NTOK];                       // amax/127 * mean|w|

__device__ __forceinline__ float silu_f(float v) { return v / (1.f + expf(-v)); }

// ---------------- tiny elementwise kernels ----------------
__global__ void silu_c_kernel(const float* __restrict__ c) {
    int i = blockIdx.x * 256 + threadIdx.x;
    if (i < BB * HID) g_sc[i] = silu_f(c[i]);
}

__global__ void gateact_kernel() {
    int i = blockIdx.x * 256 + threadIdx.x;
    if (i < BB * INTERD) {
        int b = i / INTERD, j = i - b * INTERD;
        float g = g_gy[b * 2 * INTERD + j];
        float y = g_gy[b * 2 * INTERD + INTERD + j];
        g_u[i] = silu_f(g) * y;
    }
}

// out[b,d] = sum_k A[b,k]*W[d,k] (+bias[d]); one warp per OUTPUT ELEMENT (R1 version:
// 4x weight traffic but 4x parallelism — measured faster in composition than gemm4b).
__global__ void gemm4_kernel(const float* __restrict__ A, const float* __restrict__ W,
                             const float* __restrict__ bias, float* __restrict__ out,
                             int K, int D) {
    int warp = threadIdx.x >> 5, lane = threadIdx.x & 31;
    int idx = blockIdx.x * 8 + warp;
    if (idx >= 4 * D) return;
    int b = idx / D, d = idx - b * D;
    const float* a = A + (long)b * K;
    const float* w = W + (long)d * K;
    float s = 0.f;
#pragma unroll 8
    for (int k = lane; k < K; k += 32) s += a[k] * w[k];
#pragma unroll
    for (int o = 16; o; o >>= 1) s += __shfl_xor_sync(0xffffffffu, s, o);
    if (lane == 0) out[idx] = s + (bias ? bias[d] : 0.f);
}

__global__ void rms4_kernel(const float* __restrict__ w_norm) {
    __shared__ float sm[256];
    int b = blockIdx.x, tid = threadIdx.x;
    float* o = g_o + b * 2048;
    float s = 0.f;
    for (int i = tid; i < 2048; i += 256) { float v = o[i]; s += v * v; }
    sm[tid] = s; __syncthreads();
    for (int st = 128; st > 0; st >>= 1) { if (tid < st) sm[tid] += sm[tid + st]; __syncthreads(); }
    float rstd = rsqrtf(sm[0] * (1.f / 2048.f) + 1e-6f);
    for (int i = tid; i < 2048; i += 256) o[i] = o[i] * rstd * w_norm[i];
}

// ---------------- weight quant (deterministic reduction) ----------------
__global__ void wabs_partial_kernel(const float* __restrict__ w) {
    __shared__ float sm[256];
    int b = blockIdx.x, tid = threadIdx.x;
    const float* p = w + (long)b * 1024;
    float s = 0.f;
    for (int i = tid; i < 1024; i += 256) s += fabsf(p[i]);
    sm[tid] = s; __syncthreads();
    for (int st = 128; st > 0; st >>= 1) { if (tid < st) sm[tid] += sm[tid + st]; __syncthreads(); }
    if (tid == 0) g_part[b] = sm[0];
}

__global__ void wabs_final_kernel() {
    __shared__ float sm[256];
    int tid = threadIdx.x;
    float s = g_part[tid] + g_part[tid + 256] + g_part[tid + 512] + g_part[tid + 768];
    sm[tid] = s; __syncthreads();
    for (int st = 128; st > 0; st >>= 1) { if (tid < st) sm[tid] += sm[tid + st]; __syncthreads(); }
    if (tid == 0) {
        float mean = sm[0] * (1.f / (1024.f * 1024.f));
        float m = fmaxf(mean, 1e-5f);
        g_ws[0] = 1.f / m;
        g_ws[1] = m;
    }
}

__global__ void wquant_kernel(const float* __restrict__ w) {
    int i = blockIdx.x * 256 + threadIdx.x;           // groups of 4
    if (i < ODIM * HID / 4) {
        float s = g_ws[0];
        const float4 v = ((const float4*)w)[i];
        __nv_bfloat162 lo, hi;
        lo.x = __float2bfloat16(fminf(fmaxf(rintf(v.x * s), -1.f), 1.f));
        lo.y = __float2bfloat16(fminf(fmaxf(rintf(v.y * s), -1.f), 1.f));
        hi.x = __float2bfloat16(fminf(fmaxf(rintf(v.z * s), -1.f), 1.f));
        hi.y = __float2bfloat16(fminf(fmaxf(rintf(v.w * s), -1.f), 1.f));
        ((__nv_bfloat162*)g_wq)[i * 2]     = lo;
        ((__nv_bfloat162*)g_wq)[i * 2 + 1] = hi;
    }
}

// ---------------- activation pipeline: LN -> modulate -> RMSNorm -> quant ----------------
__global__ void aq_kernel(const float* __restrict__ x, const float* __restrict__ wbn) {
    __shared__ float sm[256];
    __shared__ float sm2[256];
    int t = blockIdx.x, tid = threadIdx.x;
    int b = t >> 13;
    const float4* xr = (const float4*)(x + (long)t * HID);
    const float* mod = g_mod + b * 2048;              // [0:1024) shift, [1024:2048) scale
    float4 v = xr[tid];
    float s = v.x + v.y + v.z + v.w;
    float s2 = v.x*v.x + v.y*v.y + v.z*v.z + v.w*v.w;
    sm[tid] = s; sm2[tid] = s2; __syncthreads();
    for (int st = 128; st > 0; st >>= 1) {
        if (tid < st) { sm[tid] += sm[tid + st]; sm2[tid] += sm2[tid + st]; }
        __syncthreads();
    }
    float mean = sm[0] * (1.f / HID);
    float var = sm2[0] * (1.f / HID) - mean * mean;
    float rstd = rsqrtf(var + 1e-6f);
    __syncthreads();

    int h0 = tid * 4;
    v.x = (v.x - mean) * rstd * (1.f + mod[1024+h0])   + mod[h0];
    v.y = (v.y - mean) * rstd * (1.f + mod[1024+h0+1]) + mod[h0+1];
    v.z = (v.z - mean) * rstd * (1.f + mod[1024+h0+2]) + mod[h0+2];
    v.w = (v.w - mean) * rstd * (1.f + mod[1024+h0+3]) + mod[h0+3];
    float ms = v.x*v.x + v.y*v.y + v.z*v.z + v.w*v.w;
    sm[tid] = ms; __syncthreads();
    for (int st = 128; st > 0; st >>= 1) { if (tid < st) sm[tid] += sm[tid + st]; __syncthreads(); }
    float rr = rsqrtf(sm[0] * (1.f / HID) + 1e-8f);
    __syncthreads();

    v.x *= rr * wbn[h0];   v.y *= rr * wbn[h0+1];
    v.z *= rr * wbn[h0+2]; v.w *= rr * wbn[h0+3];
    float amax = fmaxf(fmaxf(fabsf(v.x), fabsf(v.y)), fmaxf(fabsf(v.z), fabsf(v.w)));
    sm[tid] = amax; __syncthreads();
    for (int st = 128; st > 0; st >>= 1) { if (tid < st) sm[tid] = fmaxf(sm[tid], sm[tid + st]); __syncthreads(); }
    float am = fmaxf(sm[0], 1e-5f);
    float sa = 127.f / am;
    __nv_bfloat162 q0, q1;
    q0.x = __float2bfloat16(fminf(fmaxf(rintf(v.x * sa), -128.f), 127.f));
    q0.y = __float2bfloat16(fminf(fmaxf(rintf(v.y * sa), -128.f), 127.f));
    q1.x = __float2bfloat16(fminf(fmaxf(rintf(v.z * sa), -128.f), 127.f));
    q1.y = __float2bfloat16(fminf(fmaxf(rintf(v.w * sa), -128.f), 127.f));
    __nv_bfloat162* qp = (__nv_bfloat162*)(g_q + (long)t * HID);
    qp[tid * 2]     = q0;
    qp[tid * 2 + 1] = q1;
    if (tid == 0) g_arecip[t] = am * (1.f / 127.f) * g_ws[1];
}

// ---------------- main GEMM: bf16 mma.sync + ldmatrix, BK=64, SW128 rows ----------------
__device__ __forceinline__ void cp16s(uint32_t saddr, const void* g) {
    asm volatile("cp.async.cg.shared.global [%0], [%1], 16;\n" :: "r"(saddr), "l"(g));
}

#define OPER_BYTES 16384            // 128 rows x 128 B (one operand, one stage)
#define STG_BYTES  32768            // A + B per stage
#define SW(o) ((o) ^ (((o) >> 3) & 0x70))

extern __shared__ __align__(16) char smdyn[];

__global__ void __launch_bounds__(256, 2) bitgemm_kernel(const float* __restrict__ bias,
                                                         float* __restrict__ out) {
    const int tid = threadIdx.x;
    const int lane = tid & 31, warp = tid >> 5;
    const int wm = warp >> 1, wn = warp & 1;      // 4x2 warp grid: 32 rows x 64 cols per warp
    const long arow0 = (long)blockIdx.y * 128;
    const int brow0 = blockIdx.x * 128;
    const int g = lane >> 2, tg = lane & 3;

    uint32_t sbase;
    asm("{ .reg .u64 t; cvta.to.shared.u64 t, %1; cvt.u32.u64 %0, t; }"
        : "=r"(sbase) : "l"(smdyn));

    // per-lane ldmatrix address deltas
    const int lr = lane & 7, blk = lane >> 3;
    const int rA = lr + (blk & 1) * 8, cA = (blk >> 1) * 8;    // A: blocks 0/1 rows, 2/3 +8 cols
    const int rB = lr + (blk >> 1) * 8, cB = (blk & 1) * 8;    // B: blocks 0/2 n-rows, 1/3 +8 cols

    float acc[2][8][4];
#pragma unroll
    for (int i = 0; i < 2; i++)
#pragma unroll
        for (int j = 0; j < 8; j++)
#pragma unroll
            for (int r = 0; r < 4; r++) acc[i][j][r] = 0.f;

    // loader: chunk kt (64 bf16 wide) -> stage kt&1, SW128-swizzled 128B rows
    auto load_chunk = [&](int kt) {
        const uint32_t ab = sbase + (kt & 1) * STG_BYTES;
        const uint32_t bb = ab + OPER_BYTES;
        const int k0 = kt * 64;
#pragma unroll
        for (int it = 0; it < 4; it++) {
            int idx = it * 256 + tid;                 // [0,1024)
            int row = idx >> 3, u = idx & 7;
            uint32_t off = row * 128 + u * 16;
            cp16s(ab + SW(off), g_q + (arow0 + row) * HID + k0 + u * 8);
            cp16s(bb + SW(off), g_wq + (long)(brow0 + row) * HID + k0 + u * 8);
        }
        asm volatile("cp.async.commit_group;\n");
    };

    load_chunk(0);

#pragma unroll 1
    for (int kt = 0; kt < 16; kt++) {
        if (kt < 15) {
            load_chunk(kt + 1);
            asm volatile("cp.async.wait_group 1;\n");
        } else {
            asm volatile("cp.async.wait_group 0;\n");
        }
        __syncthreads();

        const uint32_t ab = sbase + (kt & 1) * STG_BYTES;
        const uint32_t bb = ab + OPER_BYTES;
#pragma unroll
        for (int ks = 0; ks < 4; ks++) {
            const int kb = ks * 16;
            // A fragments via ldmatrix.x4 (one per m16 block)
            unsigned av[2][4];
#pragma unroll
            for (int i = 0; i < 2; i++) {
                uint32_t off = (uint32_t)(wm * 32 + i * 16 + rA) * 128 + (kb + cA) * 2;
                asm volatile("ldmatrix.sync.aligned.m8n8.x4.shared.b16 {%0,%1,%2,%3}, [%4];"
                             : "=r"(av[i][0]), "=r"(av[i][1]), "=r"(av[i][2]), "=r"(av[i][3])
                             : "r"(ab + SW(off)));
            }
            // B fragments: one x4 covers two n8 blocks (j, j+1) for both k-halves
#pragma unroll
            for (int jj = 0; jj < 4; jj++) {
                unsigned bv[4];
                uint32_t off = (uint32_t)(wn * 64 + jj * 16 + rB) * 128 + (kb + cB) * 2;
                asm volatile("ldmatrix.sync.aligned.m8n8.x4.shared.b16 {%0,%1,%2,%3}, [%4];"
                             : "=r"(bv[0]), "=r"(bv[1]), "=r"(bv[2]), "=r"(bv[3])
                             : "r"(bb + SW(off)));
#pragma unroll
                for (int jh = 0; jh < 2; jh++) {
                    int j = jj * 2 + jh;
#pragma unroll
                    for (int i = 0; i < 2; i++) {
                        asm volatile(
                            "mma.sync.aligned.m16n8k16.row.col.f32.bf16.bf16.f32 "
                            "{%0,%1,%2,%3}, {%4,%5,%6,%7}, {%8,%9}, {%0,%1,%2,%3};"
                            : "+f"(acc[i][j][0]), "+f"(acc[i][j][1]),
                              "+f"(acc[i][j][2]), "+f"(acc[i][j][3])
                            : "r"(av[i][0]), "r"(av[i][1]), "r"(av[i][2]), "r"(av[i][3]),
                              "r"(bv[jh * 2]), "r"(bv[jh * 2 + 1]));
                    }
                }
            }
        }
        __syncthreads();
    }

    // epilogue: exact int accum -> fp32 dequant per token + bias
#pragma unroll
    for (int i = 0; i < 2; i++) {
        long row = arow0 + wm * 32 + i * 16 + g;
        float r0 = g_arecip[row];
        float r1 = g_arecip[row + 8];
#pragma unroll
        for (int j = 0; j < 8; j++) {
            int col = brow0 + wn * 64 + j * 8 + 2 * tg;
            float b0v = bias[col], b1v = bias[col + 1];
            out[row * ODIM + col]           = acc[i][j][0] * r0 + b0v;
            out[row * ODIM + col + 1]       = acc[i][j][1] * r0 + b1v;
            out[(row + 8) * ODIM + col]     = acc[i][j][2] * r1 + b0v;
            out[(row + 8) * ODIM + col + 1] = acc[i][j][3] * r1 + b1v;
        }
    }
}

// ---------------- launch ----------------
extern "C" void kernel_launch(void* const* d_in, const int* in_sizes, int n_in,
                              void* d_out, int out_size) {
    const float* x        = (const float*)d_in[0];
    const float* c        = (const float*)d_in[1];
    const float* w_input  = (const float*)d_in[2];
    const float* w_gate   = (const float*)d_in[3];
    const float* w_down   = (const float*)d_in[4];
    const float* w_output = (const float*)d_in[5];
    const float* b_output = (const float*)d_in[6];
    const float* w_norm   = (const float*)d_in[7];
    const float* w_outp   = (const float*)d_in[8];
    const float* b_outp   = (const float*)d_in[9];
    const float* w_bit    = (const float*)d_in[10];
    const float* b_bit    = (const float*)d_in[11];
    const float* w_bn     = (const float*)d_in[12];
    float* out = (float*)d_out;

    float *p_sc, *p_h, *p_gy, *p_u, *p_z, *p_o, *p_mod;
    cudaGetSymbolAddress((void**)&p_sc,  g_sc);
    cudaGetSymbolAddress((void**)&p_h,   g_h);
    cudaGetSymbolAddress((void**)&p_gy,  g_gy);
    cudaGetSymbolAddress((void**)&p_u,   g_u);
    cudaGetSymbolAddress((void**)&p_z,   g_z);
    cudaGetSymbolAddress((void**)&p_o,   g_o);
    cudaGetSymbolAddress((void**)&p_mod, g_mod);

    // weight quant path (independent)
    wabs_partial_kernel<<<1024, 256>>>(w_bit);
    wabs_final_kernel<<<1, 256>>>();
    wquant_kernel<<<(ODIM * HID / 4) / 256, 256>>>(w_bit);

    // modulation chain (B=4) — R1 composition (one warp per output element)
    silu_c_kernel<<<16, 256>>>(c);
    gemm4_kernel<<<512, 256>>>(p_sc, w_input, nullptr, p_h, HID, HID);
    gemm4_kernel<<<2816, 256>>>(p_h, w_gate, nullptr, p_gy, HID, 2 * INTERD);
    gateact_kernel<<<44, 256>>>();
    gemm4_kernel<<<512, 256>>>(p_u, w_down, nullptr, p_z, INTERD, HID);
    gemm4_kernel<<<1024, 256>>>(p_z, w_output, b_output, p_o, HID, 2 * HID);
    rms4_kernel<<<4, 256>>>(w_norm);
    gemm4_kernel<<<1024, 256>>>(p_o, w_outp, b_outp, p_mod, 2 * HID, 2 * HID);

    // per-token normalize + bf16-int quantize
    aq_kernel<<<NTOK, 256>>>(x, w_bn);

    // main GEMM + dequant epilogue (ldmatrix + BK=64, dynamic smem 64KB)
    static const int smem_bytes = 2 * STG_BYTES;   // 65536
    cudaFuncSetAttribute(bitgemm_kernel, cudaFuncAttributeMaxDynamicSharedMemorySize, smem_bytes);
    dim3 ggrid(8, 256);   // n-tiles fastest: 8 column tiles share the A m-tile via L2
    bitgemm_kernel<<<ggrid, 256, smem_bytes>>>(b_bit, out);
}

// round 10
// speedup vs baseline: 2.1191x; 1.1682x over previous
#include <cuda_runtime.h>
#include <cuda_bf16.h>
#include <cstdint>

#define HID    1024
#define INTERD 2816
#define BB     4
#define NTOK   32768   // B * N = 4 * 8192
#define ODIM   1024

// ---------------- scratch (static device globals; no allocs) ----------------
__device__ float g_sc[BB * HID];
__device__ float g_h[BB * HID];
__device__ float g_gy[BB * 2 * INTERD];
__device__ float g_u[BB * INTERD];
__device__ float g_z[BB * HID];
__device__ float g_o[BB * 2 * HID];
__device__ float g_mod[BB * 2 * HID];
__device__ float g_part[1024];
__device__ float g_ws[2];                              // [0]=1/clip(mean|w|), [1]=clip(mean|w|)
__device__ __align__(16) __nv_bfloat16 g_wq[(long)ODIM * HID];   // ternary weights bf16
__device__ __align__(16) __nv_bfloat16 g_q[(long)NTOK * HID];    // quantized activations bf16 (ints)
__device__ float g_arecip[NTOK];                       // amax/127 * mean|w|

__device__ __forceinline__ float silu_f(float v) { return v / (1.f + expf(-v)); }

// ---------------- tiny elementwise kernels ----------------
__global__ void silu_c_kernel(const float* __restrict__ c) {
    int i = blockIdx.x * 256 + threadIdx.x;
    if (i < BB * HID) g_sc[i] = silu_f(c[i]);
}

__global__ void gateact_kernel() {
    int i = blockIdx.x * 256 + threadIdx.x;
    if (i < BB * INTERD) {
        int b = i / INTERD, j = i - b * INTERD;
        float g = g_gy[b * 2 * INTERD + j];
        float y = g_gy[b * 2 * INTERD + INTERD + j];
        g_u[i] = silu_f(g) * y;
    }
}

// out[b,d] = sum_k A[b,k]*W[d,k] (+bias[d]); one warp per OUTPUT ELEMENT (R1 composition,
// measured faster than the shared-weight variant).
__global__ void gemm4_kernel(const float* __restrict__ A, const float* __restrict__ W,
                             const float* __restrict__ bias, float* __restrict__ out,
                             int K, int D) {
    int warp = threadIdx.x >> 5, lane = threadIdx.x & 31;
    int idx = blockIdx.x * 8 + warp;
    if (idx >= 4 * D) return;
    int b = idx / D, d = idx - b * D;
    const float* a = A + (long)b * K;
    const float* w = W + (long)d * K;
    float s = 0.f;
#pragma unroll 8
    for (int k = lane; k < K; k += 32) s += a[k] * w[k];
#pragma unroll
    for (int o = 16; o; o >>= 1) s += __shfl_xor_sync(0xffffffffu, s, o);
    if (lane == 0) out[idx] = s + (bias ? bias[d] : 0.f);
}

__global__ void rms4_kernel(const float* __restrict__ w_norm) {
    __shared__ float sm[256];
    int b = blockIdx.x, tid = threadIdx.x;
    float* o = g_o + b * 2048;
    float s = 0.f;
    for (int i = tid; i < 2048; i += 256) { float v = o[i]; s += v * v; }
    sm[tid] = s; __syncthreads();
    for (int st = 128; st > 0; st >>= 1) { if (tid < st) sm[tid] += sm[tid + st]; __syncthreads(); }
    float rstd = rsqrtf(sm[0] * (1.f / 2048.f) + 1e-6f);
    for (int i = tid; i < 2048; i += 256) o[i] = o[i] * rstd * w_norm[i];
}

// ---------------- weight quant (deterministic reduction) ----------------
__global__ void wabs_partial_kernel(const float* __restrict__ w) {
    __shared__ float sm[256];
    int b = blockIdx.x, tid = threadIdx.x;
    const float* p = w + (long)b * 1024;
    float s = 0.f;
    for (int i = tid; i < 1024; i += 256) s += fabsf(p[i]);
    sm[tid] = s; __syncthreads();
    for (int st = 128; st > 0; st >>= 1) { if (tid < st) sm[tid] += sm[tid + st]; __syncthreads(); }
    if (tid == 0) g_part[b] = sm[0];
}

__global__ void wabs_final_kernel() {
    __shared__ float sm[256];
    int tid = threadIdx.x;
    float s = g_part[tid] + g_part[tid + 256] + g_part[tid + 512] + g_part[tid + 768];
    sm[tid] = s; __syncthreads();
    for (int st = 128; st > 0; st >>= 1) { if (tid < st) sm[tid] += sm[tid + st]; __syncthreads(); }
    if (tid == 0) {
        float mean = sm[0] * (1.f / (1024.f * 1024.f));
        float m = fmaxf(mean, 1e-5f);
        g_ws[0] = 1.f / m;
        g_ws[1] = m;
    }
}

__global__ void wquant_kernel(const float* __restrict__ w) {
    int i = blockIdx.x * 256 + threadIdx.x;           // groups of 4
    if (i < ODIM * HID / 4) {
        float s = g_ws[0];
        const float4 v = ((const float4*)w)[i];
        __nv_bfloat162 lo, hi;
        lo.x = __float2bfloat16(fminf(fmaxf(rintf(v.x * s), -1.f), 1.f));
        lo.y = __float2bfloat16(fminf(fmaxf(rintf(v.y * s), -1.f), 1.f));
        hi.x = __float2bfloat16(fminf(fmaxf(rintf(v.z * s), -1.f), 1.f));
        hi.y = __float2bfloat16(fminf(fmaxf(rintf(v.w * s), -1.f), 1.f));
        ((__nv_bfloat162*)g_wq)[i * 2]     = lo;
        ((__nv_bfloat162*)g_wq)[i * 2 + 1] = hi;
    }
}

// ---------------- activation pipeline: LN -> modulate -> RMSNorm -> quant ----------------
// Shuffle-based reductions: 6 block syncs total (was 24).
__global__ void aq_kernel(const float* __restrict__ x, const float* __restrict__ wbn) {
    __shared__ float p1[8], p2[8];
    int t = blockIdx.x, tid = threadIdx.x;
    int wid = tid >> 5, lane = tid & 31;
    int b = t >> 13;
    const float4* xr = (const float4*)(x + (long)t * HID);
    const float* mod = g_mod + b * 2048;              // [0:1024) shift, [1024:2048) scale
    float4 v = xr[tid];

    // --- pass 1: mean & var ---
    float s = v.x + v.y + v.z + v.w;
    float s2 = v.x*v.x + v.y*v.y + v.z*v.z + v.w*v.w;
#pragma unroll
    for (int o = 16; o; o >>= 1) {
        s  += __shfl_xor_sync(0xffffffffu, s, o);
        s2 += __shfl_xor_sync(0xffffffffu, s2, o);
    }
    if (lane == 0) { p1[wid] = s; p2[wid] = s2; }
    __syncthreads();
    float S = 0.f, S2 = 0.f;
#pragma unroll
    for (int i = 0; i < 8; i++) { S += p1[i]; S2 += p2[i]; }
    float mean = S * (1.f / HID);
    float var = S2 * (1.f / HID) - mean * mean;
    float rstd = rsqrtf(var + 1e-6f);
    __syncthreads();

    // --- modulate + pass 2: sum of squares ---
    int h0 = tid * 4;
    v.x = (v.x - mean) * rstd * (1.f + mod[1024+h0])   + mod[h0];
    v.y = (v.y - mean) * rstd * (1.f + mod[1024+h0+1]) + mod[h0+1];
    v.z = (v.z - mean) * rstd * (1.f + mod[1024+h0+2]) + mod[h0+2];
    v.w = (v.w - mean) * rstd * (1.f + mod[1024+h0+3]) + mod[h0+3];
    float ms = v.x*v.x + v.y*v.y + v.z*v.z + v.w*v.w;
#pragma unroll
    for (int o = 16; o; o >>= 1) ms += __shfl_xor_sync(0xffffffffu, ms, o);
    if (lane == 0) p1[wid] = ms;
    __syncthreads();
    float MS = 0.f;
#pragma unroll
    for (int i = 0; i < 8; i++) MS += p1[i];
    float rr = rsqrtf(MS * (1.f / HID) + 1e-8f);
    __syncthreads();

    // --- rms-scale + pass 3: absmax ---
    v.x *= rr * wbn[h0];   v.y *= rr * wbn[h0+1];
    v.z *= rr * wbn[h0+2]; v.w *= rr * wbn[h0+3];
    float amax = fmaxf(fmaxf(fabsf(v.x), fabsf(v.y)), fmaxf(fabsf(v.z), fabsf(v.w)));
#pragma unroll
    for (int o = 16; o; o >>= 1) amax = fmaxf(amax, __shfl_xor_sync(0xffffffffu, amax, o));
    if (lane == 0) p1[wid] = amax;
    __syncthreads();
    float AM = 0.f;
#pragma unroll
    for (int i = 0; i < 8; i++) AM = fmaxf(AM, p1[i]);
    float am = fmaxf(AM, 1e-5f);
    float sa = 127.f / am;

    __nv_bfloat162 q0, q1;
    q0.x = __float2bfloat16(fminf(fmaxf(rintf(v.x * sa), -128.f), 127.f));
    q0.y = __float2bfloat16(fminf(fmaxf(rintf(v.y * sa), -128.f), 127.f));
    q1.x = __float2bfloat16(fminf(fmaxf(rintf(v.z * sa), -128.f), 127.f));
    q1.y = __float2bfloat16(fminf(fmaxf(rintf(v.w * sa), -128.f), 127.f));
    __nv_bfloat162* qp = (__nv_bfloat162*)(g_q + (long)t * HID);
    qp[tid * 2]     = q0;
    qp[tid * 2 + 1] = q1;
    if (tid == 0) g_arecip[t] = am * (1.f / 127.f) * g_ws[1];
}

// ---------------- main GEMM: bf16 mma.sync + ldmatrix, BK=64, 3-stage, 1 sync/iter ----------------
__device__ __forceinline__ void cp16s(uint32_t saddr, const void* g) {
    asm volatile("cp.async.cg.shared.global [%0], [%1], 16;\n" :: "r"(saddr), "l"(g));
}

#define NSTG       3
#define OPER_BYTES 16384            // 128 rows x 128 B (one operand, one stage)
#define STG_BYTES  32768            // A + B per stage
#define SW(o) ((o) ^ (((o) >> 3) & 0x70))

extern __shared__ __align__(16) char smdyn[];

__global__ void __launch_bounds__(256, 2) bitgemm_kernel(const float* __restrict__ bias,
                                                         float* __restrict__ out) {
    const int tid = threadIdx.x;
    const int lane = tid & 31, warp = tid >> 5;
    const int wm = warp >> 1, wn = warp & 1;      // 4x2 warp grid: 32 rows x 64 cols per warp
    const long arow0 = (long)blockIdx.y * 128;
    const int brow0 = blockIdx.x * 128;
    const int g = lane >> 2, tg = lane & 3;

    uint32_t sbase;
    asm("{ .reg .u64 t; cvta.to.shared.u64 t, %1; cvt.u32.u64 %0, t; }"
        : "=r"(sbase) : "l"(smdyn));

    // per-lane ldmatrix address deltas
    const int lr = lane & 7, blk = lane >> 3;
    const int rA = lr + (blk & 1) * 8, cA = (blk >> 1) * 8;    // A: blocks 0/1 rows, 2/3 +8 cols
    const int rB = lr + (blk >> 1) * 8, cB = (blk & 1) * 8;    // B: blocks 0/2 n-rows, 1/3 +8 cols

    float acc[2][8][4];
#pragma unroll
    for (int i = 0; i < 2; i++)
#pragma unroll
        for (int j = 0; j < 8; j++)
#pragma unroll
            for (int r = 0; r < 4; r++) acc[i][j][r] = 0.f;

    // loader: chunk kt (64 bf16 wide) -> stage kt%3, SW128-swizzled 128B rows
    auto load_chunk = [&](int kt) {
        const uint32_t ab = sbase + (kt % NSTG) * STG_BYTES;
        const uint32_t bb = ab + OPER_BYTES;
        const int k0 = kt * 64;
#pragma unroll
        for (int it = 0; it < 4; it++) {
            int idx = it * 256 + tid;                 // [0,1024)
            int row = idx >> 3, u = idx & 7;
            uint32_t off = row * 128 + u * 16;
            cp16s(ab + SW(off), g_q + (arow0 + row) * HID + k0 + u * 8);
            cp16s(bb + SW(off), g_wq + (long)(brow0 + row) * HID + k0 + u * 8);
        }
        asm volatile("cp.async.commit_group;\n");
    };

    // prologue: 2 chunks in flight
    load_chunk(0);
    load_chunk(1);

#pragma unroll 1
    for (int kt = 0; kt < 16; kt++) {
        // chunk kt ready when <=1 group outstanding (the kt+1 load)
        if (kt < 15) asm volatile("cp.async.wait_group 1;\n");
        else         asm volatile("cp.async.wait_group 0;\n");
        __syncthreads();   // also orders last iteration's LDSM reads before the overwrite below

        if (kt + 2 < 16) load_chunk(kt + 2);   // overwrites stage (kt-1)%3 — safe after sync

        const uint32_t ab = sbase + (kt % NSTG) * STG_BYTES;
        const uint32_t bb = ab + OPER_BYTES;
#pragma unroll
        for (int ks = 0; ks < 4; ks++) {
            const int kb = ks * 16;
            unsigned av[2][4];
#pragma unroll
            for (int i = 0; i < 2; i++) {
                uint32_t off = (uint32_t)(wm * 32 + i * 16 + rA) * 128 + (kb + cA) * 2;
                asm volatile("ldmatrix.sync.aligned.m8n8.x4.shared.b16 {%0,%1,%2,%3}, [%4];"
                             : "=r"(av[i][0]), "=r"(av[i][1]), "=r"(av[i][2]), "=r"(av[i][3])
                             : "r"(ab + SW(off)));
            }
#pragma unroll
            for (int jj = 0; jj < 4; jj++) {
                unsigned bv[4];
                uint32_t off = (uint32_t)(wn * 64 + jj * 16 + rB) * 128 + (kb + cB) * 2;
                asm volatile("ldmatrix.sync.aligned.m8n8.x4.shared.b16 {%0,%1,%2,%3}, [%4];"
                             : "=r"(bv[0]), "=r"(bv[1]), "=r"(bv[2]), "=r"(bv[3])
                             : "r"(bb + SW(off)));
#pragma unroll
                for (int jh = 0; jh < 2; jh++) {
                    int j = jj * 2 + jh;
#pragma unroll
                    for (int i = 0; i < 2; i++) {
                        asm volatile(
                            "mma.sync.aligned.m16n8k16.row.col.f32.bf16.bf16.f32 "
                            "{%0,%1,%2,%3}, {%4,%5,%6,%7}, {%8,%9}, {%0,%1,%2,%3};"
                            : "+f"(acc[i][j][0]), "+f"(acc[i][j][1]),
                              "+f"(acc[i][j][2]), "+f"(acc[i][j][3])
                            : "r"(av[i][0]), "r"(av[i][1]), "r"(av[i][2]), "r"(av[i][3]),
                              "r"(bv[jh * 2]), "r"(bv[jh * 2 + 1]));
                    }
                }
            }
        }
    }

    // epilogue: exact int accum -> fp32 dequant per token + bias
#pragma unroll
    for (int i = 0; i < 2; i++) {
        long row = arow0 + wm * 32 + i * 16 + g;
        float r0 = g_arecip[row];
        float r1 = g_arecip[row + 8];
#pragma unroll
        for (int j = 0; j < 8; j++) {
            int col = brow0 + wn * 64 + j * 8 + 2 * tg;
            float b0v = bias[col], b1v = bias[col + 1];
            out[row * ODIM + col]           = acc[i][j][0] * r0 + b0v;
            out[row * ODIM + col + 1]       = acc[i][j][1] * r0 + b1v;
            out[(row + 8) * ODIM + col]     = acc[i][j][2] * r1 + b0v;
            out[(row + 8) * ODIM + col + 1] = acc[i][j][3] * r1 + b1v;
        }
    }
}

// ---------------- launch ----------------
extern "C" void kernel_launch(void* const* d_in, const int* in_sizes, int n_in,
                              void* d_out, int out_size) {
    const float* x        = (const float*)d_in[0];
    const float* c        = (const float*)d_in[1];
    const float* w_input  = (const float*)d_in[2];
    const float* w_gate   = (const float*)d_in[3];
    const float* w_down   = (const float*)d_in[4];
    const float* w_output = (const float*)d_in[5];
    const float* b_output = (const float*)d_in[6];
    const float* w_norm   = (const float*)d_in[7];
    const float* w_outp   = (const float*)d_in[8];
    const float* b_outp   = (const float*)d_in[9];
    const float* w_bit    = (const float*)d_in[10];
    const float* b_bit    = (const float*)d_in[11];
    const float* w_bn     = (const float*)d_in[12];
    float* out = (float*)d_out;

    float *p_sc, *p_h, *p_gy, *p_u, *p_z, *p_o, *p_mod;
    cudaGetSymbolAddress((void**)&p_sc,  g_sc);
    cudaGetSymbolAddress((void**)&p_h,   g_h);
    cudaGetSymbolAddress((void**)&p_gy,  g_gy);
    cudaGetSymbolAddress((void**)&p_u,   g_u);
    cudaGetSymbolAddress((void**)&p_z,   g_z);
    cudaGetSymbolAddress((void**)&p_o,   g_o);
    cudaGetSymbolAddress((void**)&p_mod, g_mod);

    // weight quant path (independent)
    wabs_partial_kernel<<<1024, 256>>>(w_bit);
    wabs_final_kernel<<<1, 256>>>();
    wquant_kernel<<<(ODIM * HID / 4) / 256, 256>>>(w_bit);

    // modulation chain (B=4) — R1 composition (one warp per output element)
    silu_c_kernel<<<16, 256>>>(c);
    gemm4_kernel<<<512, 256>>>(p_sc, w_input, nullptr, p_h, HID, HID);
    gemm4_kernel<<<2816, 256>>>(p_h, w_gate, nullptr, p_gy, HID, 2 * INTERD);
    gateact_kernel<<<44, 256>>>();
    gemm4_kernel<<<512, 256>>>(p_u, w_down, nullptr, p_z, INTERD, HID);
    gemm4_kernel<<<1024, 256>>>(p_z, w_output, b_output, p_o, HID, 2 * HID);
    rms4_kernel<<<4, 256>>>(w_norm);
    gemm4_kernel<<<1024, 256>>>(p_o, w_outp, b_outp, p_mod, 2 * HID, 2 * HID);

    // per-token normalize + bf16-int quantize (shuffle reductions)
    aq_kernel<<<NTOK, 256>>>(x, w_bn);

    // main GEMM + dequant epilogue (ldmatrix + BK=64, 3-stage, dynamic smem 96KB)
    static const int smem_bytes = NSTG * STG_BYTES;   // 98304
    cudaFuncSetAttribute(bitgemm_kernel, cudaFuncAttributeMaxDynamicSharedMemorySize, smem_bytes);
    dim3 ggrid(8, 256);   // n-tiles fastest: 8 column tiles share the A m-tile via L2
    bitgemm_kernel<<<ggrid, 256, smem_bytes>>>(b_bit, out);
}

// round 11
// speedup vs baseline: 2.1988x; 1.0376x over previous
#include <cuda_runtime.h>
#include <cuda_bf16.h>
#include <cstdint>

#define HID    1024
#define INTERD 2816
#define BB     4
#define NTOK   32768   // B * N = 4 * 8192
#define ODIM   1024

// ---------------- scratch (static device globals; no allocs) ----------------
__device__ float g_sc[BB * HID];
__device__ float g_h[BB * HID];
__device__ float g_gy[BB * 2 * INTERD];
__device__ float g_u[BB * INTERD];
__device__ float g_z[BB * HID];
__device__ float g_o[BB * 2 * HID];
__device__ float g_mod[BB * 2 * HID];
__device__ float g_part[1024];
__device__ float g_ws[2];                              // [0]=1/clip(mean|w|), [1]=clip(mean|w|)
__device__ __align__(16) __nv_bfloat16 g_wq[(long)ODIM * HID];   // ternary weights bf16
__device__ __align__(16) __nv_bfloat16 g_q[(long)NTOK * HID];    // quantized activations bf16 (ints)
__device__ float g_arecip[NTOK];                       // amax/127 * mean|w|

__device__ __forceinline__ float silu_f(float v) { return v / (1.f + expf(-v)); }

// ---------------- tiny elementwise kernels ----------------
__global__ void silu_c_kernel(const float* __restrict__ c) {
    int i = blockIdx.x * 256 + threadIdx.x;
    if (i < BB * HID) g_sc[i] = silu_f(c[i]);
}

__global__ void gateact_kernel() {
    int i = blockIdx.x * 256 + threadIdx.x;
    if (i < BB * INTERD) {
        int b = i / INTERD, j = i - b * INTERD;
        float g = g_gy[b * 2 * INTERD + j];
        float y = g_gy[b * 2 * INTERD + INTERD + j];
        g_u[i] = silu_f(g) * y;
    }
}

// out[b,d] = sum_k A[b,k]*W[d,k] (+bias[d]); one warp per OUTPUT ELEMENT.
// float4-vectorized loads: 4x fewer LDG issues, higher MLP (chain is latency-bound).
__global__ void gemm4_kernel(const float* __restrict__ A, const float* __restrict__ W,
                             const float* __restrict__ bias, float* __restrict__ out,
                             int K, int D) {
    int warp = threadIdx.x >> 5, lane = threadIdx.x & 31;
    int idx = blockIdx.x * 8 + warp;
    if (idx >= 4 * D) return;
    int b = idx / D, d = idx - b * D;
    const float4* a = (const float4*)(A + (long)b * K);
    const float4* w = (const float4*)(W + (long)d * K);
    int K4 = K >> 2;
    float s = 0.f;
#pragma unroll 8
    for (int k = lane; k < K4; k += 32) {
        float4 av = a[k], wv = w[k];
        s += av.x * wv.x + av.y * wv.y + av.z * wv.z + av.w * wv.w;
    }
#pragma unroll
    for (int o = 16; o; o >>= 1) s += __shfl_xor_sync(0xffffffffu, s, o);
    if (lane == 0) out[idx] = s + (bias ? bias[d] : 0.f);
}

__global__ void rms4_kernel(const float* __restrict__ w_norm) {
    __shared__ float sm[256];
    int b = blockIdx.x, tid = threadIdx.x;
    float* o = g_o + b * 2048;
    float s = 0.f;
    for (int i = tid; i < 2048; i += 256) { float v = o[i]; s += v * v; }
    sm[tid] = s; __syncthreads();
    for (int st = 128; st > 0; st >>= 1) { if (tid < st) sm[tid] += sm[tid + st]; __syncthreads(); }
    float rstd = rsqrtf(sm[0] * (1.f / 2048.f) + 1e-6f);
    for (int i = tid; i < 2048; i += 256) o[i] = o[i] * rstd * w_norm[i];
}

// ---------------- weight quant (deterministic reduction) ----------------
__global__ void wabs_partial_kernel(const float* __restrict__ w) {
    __shared__ float sm[256];
    int b = blockIdx.x, tid = threadIdx.x;
    const float* p = w + (long)b * 1024;
    float s = 0.f;
    for (int i = tid; i < 1024; i += 256) s += fabsf(p[i]);
    sm[tid] = s; __syncthreads();
    for (int st = 128; st > 0; st >>= 1) { if (tid < st) sm[tid] += sm[tid + st]; __syncthreads(); }
    if (tid == 0) g_part[b] = sm[0];
}

__global__ void wabs_final_kernel() {
    __shared__ float sm[256];
    int tid = threadIdx.x;
    float s = g_part[tid] + g_part[tid + 256] + g_part[tid + 512] + g_part[tid + 768];
    sm[tid] = s; __syncthreads();
    for (int st = 128; st > 0; st >>= 1) { if (tid < st) sm[tid] += sm[tid + st]; __syncthreads(); }
    if (tid == 0) {
        float mean = sm[0] * (1.f / (1024.f * 1024.f));
        float m = fmaxf(mean, 1e-5f);
        g_ws[0] = 1.f / m;
        g_ws[1] = m;
    }
}

__global__ void wquant_kernel(const float* __restrict__ w) {
    int i = blockIdx.x * 256 + threadIdx.x;           // groups of 4
    if (i < ODIM * HID / 4) {
        float s = g_ws[0];
        const float4 v = ((const float4*)w)[i];
        __nv_bfloat162 lo, hi;
        lo.x = __float2bfloat16(fminf(fmaxf(rintf(v.x * s), -1.f), 1.f));
        lo.y = __float2bfloat16(fminf(fmaxf(rintf(v.y * s), -1.f), 1.f));
        hi.x = __float2bfloat16(fminf(fmaxf(rintf(v.z * s), -1.f), 1.f));
        hi.y = __float2bfloat16(fminf(fmaxf(rintf(v.w * s), -1.f), 1.f));
        ((__nv_bfloat162*)g_wq)[i * 2]     = lo;
        ((__nv_bfloat162*)g_wq)[i * 2 + 1] = hi;
    }
}

// ---------------- activation pipeline: LN -> modulate -> RMSNorm -> quant ----------------
// Shuffle-based reductions (R10, measured win).
__global__ void aq_kernel(const float* __restrict__ x, const float* __restrict__ wbn) {
    __shared__ float p1[8], p2[8];
    int t = blockIdx.x, tid = threadIdx.x;
    int wid = tid >> 5, lane = tid & 31;
    int b = t >> 13;
    const float4* xr = (const float4*)(x + (long)t * HID);
    const float* mod = g_mod + b * 2048;              // [0:1024) shift, [1024:2048) scale
    float4 v = xr[tid];

    // --- pass 1: mean & var ---
    float s = v.x + v.y + v.z + v.w;
    float s2 = v.x*v.x + v.y*v.y + v.z*v.z + v.w*v.w;
#pragma unroll
    for (int o = 16; o; o >>= 1) {
        s  += __shfl_xor_sync(0xffffffffu, s, o);
        s2 += __shfl_xor_sync(0xffffffffu, s2, o);
    }
    if (lane == 0) { p1[wid] = s; p2[wid] = s2; }
    __syncthreads();
    float S = 0.f, S2 = 0.f;
#pragma unroll
    for (int i = 0; i < 8; i++) { S += p1[i]; S2 += p2[i]; }
    float mean = S * (1.f / HID);
    float var = S2 * (1.f / HID) - mean * mean;
    float rstd = rsqrtf(var + 1e-6f);
    __syncthreads();

    // --- modulate + pass 2: sum of squares ---
    int h0 = tid * 4;
    v.x = (v.x - mean) * rstd * (1.f + mod[1024+h0])   + mod[h0];
    v.y = (v.y - mean) * rstd * (1.f + mod[1024+h0+1]) + mod[h0+1];
    v.z = (v.z - mean) * rstd * (1.f + mod[1024+h0+2]) + mod[h0+2];
    v.w = (v.w - mean) * rstd * (1.f + mod[1024+h0+3]) + mod[h0+3];
    float ms = v.x*v.x + v.y*v.y + v.z*v.z + v.w*v.w;
#pragma unroll
    for (int o = 16; o; o >>= 1) ms += __shfl_xor_sync(0xffffffffu, ms, o);
    if (lane == 0) p1[wid] = ms;
    __syncthreads();
    float MS = 0.f;
#pragma unroll
    for (int i = 0; i < 8; i++) MS += p1[i];
    float rr = rsqrtf(MS * (1.f / HID) + 1e-8f);
    __syncthreads();

    // --- rms-scale + pass 3: absmax ---
    v.x *= rr * wbn[h0];   v.y *= rr * wbn[h0+1];
    v.z *= rr * wbn[h0+2]; v.w *= rr * wbn[h0+3];
    float amax = fmaxf(fmaxf(fabsf(v.x), fabsf(v.y)), fmaxf(fabsf(v.z), fabsf(v.w)));
#pragma unroll
    for (int o = 16; o; o >>= 1) amax = fmaxf(amax, __shfl_xor_sync(0xffffffffu, amax, o));
    if (lane == 0) p1[wid] = amax;
    __syncthreads();
    float AM = 0.f;
#pragma unroll
    for (int i = 0; i < 8; i++) AM = fmaxf(AM, p1[i]);
    float am = fmaxf(AM, 1e-5f);
    float sa = 127.f / am;

    __nv_bfloat162 q0, q1;
    q0.x = __float2bfloat16(fminf(fmaxf(rintf(v.x * sa), -128.f), 127.f));
    q0.y = __float2bfloat16(fminf(fmaxf(rintf(v.y * sa), -128.f), 127.f));
    q1.x = __float2bfloat16(fminf(fmaxf(rintf(v.z * sa), -128.f), 127.f));
    q1.y = __float2bfloat16(fminf(fmaxf(rintf(v.w * sa), -128.f), 127.f));
    __nv_bfloat162* qp = (__nv_bfloat162*)(g_q + (long)t * HID);
    qp[tid * 2]     = q0;
    qp[tid * 2 + 1] = q1;
    if (tid == 0) g_arecip[t] = am * (1.f / 127.f) * g_ws[1];
}

// ---------------- main GEMM: bf16 mma.sync + ldmatrix, BK=64, 3-stage, 1 sync/iter ----------------
__device__ __forceinline__ void cp16s(uint32_t saddr, const void* g) {
    asm volatile("cp.async.cg.shared.global [%0], [%1], 16;\n" :: "r"(saddr), "l"(g));
}

#define NSTG       3
#define OPER_BYTES 16384            // 128 rows x 128 B (one operand, one stage)
#define STG_BYTES  32768            // A + B per stage
#define SW(o) ((o) ^ (((o) >> 3) & 0x70))

extern __shared__ __align__(16) char smdyn[];

__global__ void __launch_bounds__(256, 2) bitgemm_kernel(const float* __restrict__ bias,
                                                         float* __restrict__ out) {
    const int tid = threadIdx.x;
    const int lane = tid & 31, warp = tid >> 5;
    const int wm = warp >> 1, wn = warp & 1;      // 4x2 warp grid: 32 rows x 64 cols per warp
    const long arow0 = (long)blockIdx.y * 128;
    const int brow0 = blockIdx.x * 128;
    const int g = lane >> 2, tg = lane & 3;

    uint32_t sbase;
    asm("{ .reg .u64 t; cvta.to.shared.u64 t, %1; cvt.u32.u64 %0, t; }"
        : "=r"(sbase) : "l"(smdyn));

    // per-lane ldmatrix address deltas
    const int lr = lane & 7, blk = lane >> 3;
    const int rA = lr + (blk & 1) * 8, cA = (blk >> 1) * 8;    // A: blocks 0/1 rows, 2/3 +8 cols
    const int rB = lr + (blk >> 1) * 8, cB = (blk & 1) * 8;    // B: blocks 0/2 n-rows, 1/3 +8 cols

    float acc[2][8][4];
#pragma unroll
    for (int i = 0; i < 2; i++)
#pragma unroll
        for (int j = 0; j < 8; j++)
#pragma unroll
            for (int r = 0; r < 4; r++) acc[i][j][r] = 0.f;

    // loader: chunk kt (64 bf16 wide) -> stage kt%3, SW128-swizzled 128B rows
    auto load_chunk = [&](int kt) {
        const uint32_t ab = sbase + (kt % NSTG) * STG_BYTES;
        const uint32_t bb = ab + OPER_BYTES;
        const int k0 = kt * 64;
#pragma unroll
        for (int it = 0; it < 4; it++) {
            int idx = it * 256 + tid;                 // [0,1024)
            int row = idx >> 3, u = idx & 7;
            uint32_t off = row * 128 + u * 16;
            cp16s(ab + SW(off), g_q + (arow0 + row) * HID + k0 + u * 8);
            cp16s(bb + SW(off), g_wq + (long)(brow0 + row) * HID + k0 + u * 8);
        }
        asm volatile("cp.async.commit_group;\n");
    };

    // prologue: 2 chunks in flight
    load_chunk(0);
    load_chunk(1);

#pragma unroll 1
    for (int kt = 0; kt < 16; kt++) {
        // chunk kt ready when <=1 group outstanding (the kt+1 load)
        if (kt < 15) asm volatile("cp.async.wait_group 1;\n");
        else         asm volatile("cp.async.wait_group 0;\n");
        __syncthreads();   // also orders last iteration's LDSM reads before the overwrite below

        if (kt + 2 < 16) load_chunk(kt + 2);   // overwrites stage (kt-1)%3 — safe after sync

        const uint32_t ab = sbase + (kt % NSTG) * STG_BYTES;
        const uint32_t bb = ab + OPER_BYTES;
#pragma unroll
        for (int ks = 0; ks < 4; ks++) {
            const int kb = ks * 16;
            unsigned av[2][4];
#pragma unroll
            for (int i = 0; i < 2; i++) {
                uint32_t off = (uint32_t)(wm * 32 + i * 16 + rA) * 128 + (kb + cA) * 2;
                asm volatile("ldmatrix.sync.aligned.m8n8.x4.shared.b16 {%0,%1,%2,%3}, [%4];"
                             : "=r"(av[i][0]), "=r"(av[i][1]), "=r"(av[i][2]), "=r"(av[i][3])
                             : "r"(ab + SW(off)));
            }
#pragma unroll
            for (int jj = 0; jj < 4; jj++) {
                unsigned bv[4];
                uint32_t off = (uint32_t)(wn * 64 + jj * 16 + rB) * 128 + (kb + cB) * 2;
                asm volatile("ldmatrix.sync.aligned.m8n8.x4.shared.b16 {%0,%1,%2,%3}, [%4];"
                             : "=r"(bv[0]), "=r"(bv[1]), "=r"(bv[2]), "=r"(bv[3])
                             : "r"(bb + SW(off)));
#pragma unroll
                for (int jh = 0; jh < 2; jh++) {
                    int j = jj * 2 + jh;
#pragma unroll
                    for (int i = 0; i < 2; i++) {
                        asm volatile(
                            "mma.sync.aligned.m16n8k16.row.col.f32.bf16.bf16.f32 "
                            "{%0,%1,%2,%3}, {%4,%5,%6,%7}, {%8,%9}, {%0,%1,%2,%3};"
                            : "+f"(acc[i][j][0]), "+f"(acc[i][j][1]),
                              "+f"(acc[i][j][2]), "+f"(acc[i][j][3])
                            : "r"(av[i][0]), "r"(av[i][1]), "r"(av[i][2]), "r"(av[i][3]),
                              "r"(bv[jh * 2]), "r"(bv[jh * 2 + 1]));
                    }
                }
            }
        }
    }

    // epilogue: exact int accum -> fp32 dequant per token + bias (float2 stores)
#pragma unroll
    for (int i = 0; i < 2; i++) {
        long row = arow0 + wm * 32 + i * 16 + g;
        float r0 = g_arecip[row];
        float r1 = g_arecip[row + 8];
#pragma unroll
        for (int j = 0; j < 8; j++) {
            int col = brow0 + wn * 64 + j * 8 + 2 * tg;
            float b0v = bias[col], b1v = bias[col + 1];
            float2 lo = make_float2(acc[i][j][0] * r0 + b0v, acc[i][j][1] * r0 + b1v);
            float2 hi = make_float2(acc[i][j][2] * r1 + b0v, acc[i][j][3] * r1 + b1v);
            *(float2*)(out + row * ODIM + col)       = lo;
            *(float2*)(out + (row + 8) * ODIM + col) = hi;
        }
    }
}

// ---------------- launch ----------------
extern "C" void kernel_launch(void* const* d_in, const int* in_sizes, int n_in,
                              void* d_out, int out_size) {
    const float* x        = (const float*)d_in[0];
    const float* c        = (const float*)d_in[1];
    const float* w_input  = (const float*)d_in[2];
    const float* w_gate   = (const float*)d_in[3];
    const float* w_down   = (const float*)d_in[4];
    const float* w_output = (const float*)d_in[5];
    const float* b_output = (const float*)d_in[6];
    const float* w_norm   = (const float*)d_in[7];
    const float* w_outp   = (const float*)d_in[8];
    const float* b_outp   = (const float*)d_in[9];
    const float* w_bit    = (const float*)d_in[10];
    const float* b_bit    = (const float*)d_in[11];
    const float* w_bn     = (const float*)d_in[12];
    float* out = (float*)d_out;

    float *p_sc, *p_h, *p_gy, *p_u, *p_z, *p_o, *p_mod;
    cudaGetSymbolAddress((void**)&p_sc,  g_sc);
    cudaGetSymbolAddress((void**)&p_h,   g_h);
    cudaGetSymbolAddress((void**)&p_gy,  g_gy);
    cudaGetSymbolAddress((void**)&p_u,   g_u);
    cudaGetSymbolAddress((void**)&p_z,   g_z);
    cudaGetSymbolAddress((void**)&p_o,   g_o);
    cudaGetSymbolAddress((void**)&p_mod, g_mod);

    // weight quant path (independent)
    wabs_partial_kernel<<<1024, 256>>>(w_bit);
    wabs_final_kernel<<<1, 256>>>();
    wquant_kernel<<<(ODIM * HID / 4) / 256, 256>>>(w_bit);

    // modulation chain (B=4) — one warp per output element, float4 loads
    silu_c_kernel<<<16, 256>>>(c);
    gemm4_kernel<<<512, 256>>>(p_sc, w_input, nullptr, p_h, HID, HID);
    gemm4_kernel<<<2816, 256>>>(p_h, w_gate, nullptr, p_gy, HID, 2 * INTERD);
    gateact_kernel<<<44, 256>>>();
    gemm4_kernel<<<512, 256>>>(p_u, w_down, nullptr, p_z, INTERD, HID);
    gemm4_kernel<<<1024, 256>>>(p_z, w_output, b_output, p_o, HID, 2 * HID);
    rms4_kernel<<<4, 256>>>(w_norm);
    gemm4_kernel<<<1024, 256>>>(p_o, w_outp, b_outp, p_mod, 2 * HID, 2 * HID);

    // per-token normalize + bf16-int quantize (shuffle reductions)
    aq_kernel<<<NTOK, 256>>>(x, w_bn);

    // main GEMM + dequant epilogue (ldmatrix + BK=64, 3-stage, dynamic smem 96KB)
    static const int smem_bytes = NSTG * STG_BYTES;   // 98304
    cudaFuncSetAttribute(bitgemm_kernel, cudaFuncAttributeMaxDynamicSharedMemorySize, smem_bytes);
    dim3 ggrid(8, 256);   // n-tiles fastest: 8 column tiles share the A m-tile via L2
    bitgemm_kernel<<<ggrid, 256, smem_bytes>>>(b_bit, out);
}